// round 13
// baseline (speedup 1.0000x reference)
#include <cuda_runtime.h>
#include <cuda_bf16.h>

#define K_F 16
#define T_TYPES 4
#define OUT_W (K_F * T_TYPES)
#define PI_F 3.14159265358979323846f
#define BLK 256
#define EDGES_PER_ITER 512              // 2 per thread, front-batched
#define NBLK_PERSIST 592                // 4 blocks/SM * 148
#define PACK_CAP_WORDS 14336            // 57344 B smem -> V <= 114688
#define TYPE_CAP (1 << 20)

// packed 4-bit types: node v -> nibble (0..3 = type, 0xF = no match)
__device__ unsigned int g_pack[PACK_CAP_WORDS];
// byte fallback table for PACK_CAP < V <= TYPE_CAP
__device__ signed char g_type[TYPE_CAP];

__global__ void prep_kernel(float4* __restrict__ out4, int n4,
                            const float* __restrict__ feat,
                            const float* __restrict__ ftu,
                            int V, int nwords, int mode)
{
    int i = blockIdx.x * blockDim.x + threadIdx.x;
    if (i < n4) out4[i] = make_float4(0.f, 0.f, 0.f, 0.f);
    if (mode == 2 && i < nwords) {
        unsigned int w = 0;
        #pragma unroll
        for (int j = 0; j < 8; j++) {
            int v = i * 8 + j;
            unsigned int nib = 0xF;
            if (v < V) {
                float fv = feat[v];
                #pragma unroll
                for (int t = 0; t < T_TYPES; t++)
                    if (fv == ftu[t]) nib = (unsigned int)t;
            }
            w |= nib << (4 * j);
        }
        g_pack[i] = w;
    } else if (mode == 1 && i < V) {
        float fv = feat[i];
        signed char t = -1;
        #pragma unroll
        for (int j = 0; j < T_TYPES; j++)
            if (fv == ftu[j]) t = (signed char)j;
        g_type[i] = t;
    }
}

// Fast path: persistent blocks, packed type table in smem (random gathers go
// through the smem crossbar ~3-4 cyc/warp instead of ~32 L1tex wavefronts),
// quad-cooperative compute + quad-coalesced red.v4 (R11 pattern).
__global__ void __launch_bounds__(BLK) edge_kernel_smem(
    const float* __restrict__ dist,
    const int*   __restrict__ src,
    const int*   __restrict__ dst,
    const float* __restrict__ cutoffs,
    const float* __restrict__ means,
    const float* __restrict__ scaling,
    float*       __restrict__ out,
    int E, int nwords, int per_blk)
{
    extern __shared__ unsigned int s_pack[];
    __shared__ int s_unicos;

    int tid  = threadIdx.x;
    int warp = tid >> 5;
    int lane = tid & 31;
    int c    = lane & 3;

    // Load packed table once per block (coalesced).
    for (int i = tid; i < nwords; i += BLK) s_pack[i] = g_pack[i];

    if (tid == 0) {
        int u = 1;
        #pragma unroll
        for (int k = 1; k < K_F; k++) u &= (cutoffs[k] == cutoffs[0]);
        s_unicos = u;
    }

    // Per-lane radial params (this lane's 4 k's) -> registers.
    float m[4], ns[4], cu4[4], picu[4];
    #pragma unroll
    for (int k = 0; k < 4; k++) {
        m[k]    = __ldg(&means[4 * c + k]);
        ns[k]   = -__ldg(&scaling[4 * c + k]);
        cu4[k]  = __ldg(&cutoffs[4 * c + k]);
        picu[k] = PI_F / cu4[k];
    }
    float cu0   = __ldg(&cutoffs[0]);
    float picu0 = PI_F / cu0;

    __syncthreads();
    int unicos = s_unicos;
    int qbase = lane & ~3;

    int start = blockIdx.x * per_blk;
    int end   = start + per_blk;
    if (end > E) end = E;

    for (int base = start; base < end; base += EDGES_PER_ITER) {
        int wb = base + warp * 64;
        int e0 = wb + lane;
        int e1 = wb + 32 + lane;
        bool ok0 = (e0 < end), ok1 = (e1 < end);

        float d0 = 0.f, d1 = 0.f;
        int s0 = 0, s1 = 0, dd0 = 0, dd1 = 0;
        if (ok0) { d0 = dist[e0]; s0 = src[e0]; dd0 = dst[e0]; }
        if (ok1) { d1 = dist[e1]; s1 = src[e1]; dd1 = dst[e1]; }

        // smem nibble lookup (crossbar, ~29cyc latency)
        unsigned int ty0 = 0xF, ty1 = 0xF;
        if (ok0) ty0 = (s_pack[s0 >> 3] >> ((s0 & 7) << 2)) & 0xF;
        if (ok1) ty1 = (s_pack[s1 >> 3] >> ((s1 & 7) << 2)) & 0xF;
        int code0 = (ty0 < T_TYPES) ? (dd0 * T_TYPES + (int)ty0) : -1;
        int code1 = (ty1 < T_TYPES) ? (dd1 * T_TYPES + (int)ty1) : -1;

        // Uniform-cutoff: one cosine per edge, computed by the owning lane
        // and shfl'd with d (saves 3 redundant cos per edge).
        float cv0 = 0.f, cv1 = 0.f;
        if (unicos) {
            cv0 = (d0 <= cu0) ? 0.5f * (__cosf(picu0 * d0) + 1.0f) : 0.0f;
            cv1 = (d1 <= cu0) ? 0.5f * (__cosf(picu0 * d1) + 1.0f) : 0.0f;
        }

        #pragma unroll
        for (int pass = 0; pass < 2; pass++) {
            float dp  = pass ? d1 : d0;
            float cvp = pass ? cv1 : cv0;
            int   cp  = pass ? code1 : code0;

            #pragma unroll
            for (int i = 0; i < 4; i++) {
                int srcl = qbase | i;
                float di = __shfl_sync(0xffffffffu, dp, srcl);
                int   ci = __shfl_sync(0xffffffffu, cp, srcl);

                float v0, v1, v2, v3;
                if (unicos) {
                    float cv = __shfl_sync(0xffffffffu, cvp, srcl);
                    float dm0 = di - m[0], dm1 = di - m[1];
                    float dm2 = di - m[2], dm3 = di - m[3];
                    v0 = cv * __expf(ns[0] * dm0 * dm0);
                    v1 = cv * __expf(ns[1] * dm1 * dm1);
                    v2 = cv * __expf(ns[2] * dm2 * dm2);
                    v3 = cv * __expf(ns[3] * dm3 * dm3);
                } else {
                    float v[4];
                    #pragma unroll
                    for (int k = 0; k < 4; k++) {
                        float cv = (di <= cu4[k])
                                 ? 0.5f * (__cosf(picu[k] * di) + 1.0f) : 0.0f;
                        float dm = di - m[k];
                        v[k] = cv * __expf(ns[k] * dm * dm);
                    }
                    v0 = v[0]; v1 = v[1]; v2 = v[2]; v3 = v[3];
                }

                if (ci >= 0) {
                    float* addr = out + ((size_t)ci << 4) + (c << 2);
                    asm volatile(
                        "red.global.add.v4.f32 [%0], {%1, %2, %3, %4};"
                        :: "l"(addr), "f"(v0), "f"(v1), "f"(v2), "f"(v3)
                        : "memory");
                }
            }
        }
    }
}

// Fallback (V too large for smem table): R11 quad-cooperative kernel.
__global__ void __launch_bounds__(BLK) edge_kernel_fb(
    const float* __restrict__ feat,
    const float* __restrict__ dist,
    const int*   __restrict__ src,
    const int*   __restrict__ dst,
    const float* __restrict__ cutoffs,
    const float* __restrict__ means,
    const float* __restrict__ scaling,
    const float* __restrict__ ftu,
    float*       __restrict__ out,
    int E, int use_table)
{
    __shared__ float s_ftu[T_TYPES];
    __shared__ int s_unicos;

    int tid  = threadIdx.x;
    int warp = tid >> 5;
    int lane = tid & 31;
    int c    = lane & 3;

    if (tid < T_TYPES) s_ftu[tid] = ftu[tid];
    if (tid == 0) {
        int u = 1;
        #pragma unroll
        for (int k = 1; k < K_F; k++) u &= (cutoffs[k] == cutoffs[0]);
        s_unicos = u;
    }

    float m[4], ns[4], cu4[4], picu[4];
    #pragma unroll
    for (int k = 0; k < 4; k++) {
        m[k]    = __ldg(&means[4 * c + k]);
        ns[k]   = -__ldg(&scaling[4 * c + k]);
        cu4[k]  = __ldg(&cutoffs[4 * c + k]);
        picu[k] = PI_F / cu4[k];
    }
    float cu0   = __ldg(&cutoffs[0]);
    float picu0 = PI_F / cu0;

    __syncthreads();
    int unicos = s_unicos;

    int wbase = (blockIdx.x * (BLK / 32) + warp) * 64;
    int e0 = wbase + lane;
    int e1 = wbase + 32 + lane;
    bool ok0 = (e0 < E), ok1 = (e1 < E);

    float d0 = 0.f, d1 = 0.f;
    int s0 = 0, s1 = 0, dd0 = 0, dd1 = 0;
    if (ok0) { d0 = dist[e0]; s0 = src[e0]; dd0 = dst[e0]; }
    if (ok1) { d1 = dist[e1]; s1 = src[e1]; dd1 = dst[e1]; }

    int ty0 = -1, ty1 = -1;
    if (use_table) {
        if (ok0) ty0 = g_type[s0];
        if (ok1) ty1 = g_type[s1];
    } else {
        float fv0 = ok0 ? __ldg(&feat[s0]) : -1.f;
        float fv1 = ok1 ? __ldg(&feat[s1]) : -1.f;
        #pragma unroll
        for (int j = 0; j < T_TYPES; j++) {
            if (ok0 && fv0 == s_ftu[j]) ty0 = j;
            if (ok1 && fv1 == s_ftu[j]) ty1 = j;
        }
    }
    int code0 = (ty0 >= 0) ? (dd0 * T_TYPES + ty0) : -1;
    int code1 = (ty1 >= 0) ? (dd1 * T_TYPES + ty1) : -1;

    int qbase = lane & ~3;

    #pragma unroll
    for (int pass = 0; pass < 2; pass++) {
        float dp = pass ? d1 : d0;
        int   cp = pass ? code1 : code0;

        #pragma unroll
        for (int i = 0; i < 4; i++) {
            int srcl = qbase | i;
            float di = __shfl_sync(0xffffffffu, dp, srcl);
            int   ci = __shfl_sync(0xffffffffu, cp, srcl);

            float v0, v1, v2, v3;
            if (unicos) {
                float cv = (di <= cu0)
                         ? 0.5f * (__cosf(picu0 * di) + 1.0f) : 0.0f;
                float dm0 = di - m[0], dm1 = di - m[1];
                float dm2 = di - m[2], dm3 = di - m[3];
                v0 = cv * __expf(ns[0] * dm0 * dm0);
                v1 = cv * __expf(ns[1] * dm1 * dm1);
                v2 = cv * __expf(ns[2] * dm2 * dm2);
                v3 = cv * __expf(ns[3] * dm3 * dm3);
            } else {
                float v[4];
                #pragma unroll
                for (int k = 0; k < 4; k++) {
                    float cv = (di <= cu4[k])
                             ? 0.5f * (__cosf(picu[k] * di) + 1.0f) : 0.0f;
                    float dm = di - m[k];
                    v[k] = cv * __expf(ns[k] * dm * dm);
                }
                v0 = v[0]; v1 = v[1]; v2 = v[2]; v3 = v[3];
            }

            if (ci >= 0) {
                float* addr = out + ((size_t)ci << 4) + (c << 2);
                asm volatile(
                    "red.global.add.v4.f32 [%0], {%1, %2, %3, %4};"
                    :: "l"(addr), "f"(v0), "f"(v1), "f"(v2), "f"(v3)
                    : "memory");
            }
        }
    }
}

extern "C" void kernel_launch(void* const* d_in, const int* in_sizes, int n_in,
                              void* d_out, int out_size)
{
    const float* feat    = (const float*)d_in[0];
    const float* dist    = (const float*)d_in[1];
    const int*   src     = (const int*)  d_in[2];
    const int*   dst     = (const int*)  d_in[3];
    const float* cutoffs = (const float*)d_in[4];
    const float* means   = (const float*)d_in[5];
    const float* scaling = (const float*)d_in[6];
    const float* ftu     = (const float*)d_in[7];
    float* out = (float*)d_out;

    int E = in_sizes[2];
    int V = in_sizes[0];
    int nwords = (V + 7) / 8;

    int mode;                       // 2 = smem packed, 1 = global byte, 0 = inline
    if (nwords <= PACK_CAP_WORDS)       mode = 2;
    else if (V <= TYPE_CAP)             mode = 1;
    else                                mode = 0;

    int n4 = out_size / 4;
    int prep_threads = n4 > V ? n4 : V;
    prep_kernel<<<(prep_threads + 255) / 256, 256>>>(
        (float4*)out, n4, feat, ftu, V, nwords, mode);

    if (mode == 2) {
        size_t smem = (size_t)nwords * sizeof(unsigned int);
        cudaFuncSetAttribute(edge_kernel_smem,
                             cudaFuncAttributeMaxDynamicSharedMemorySize,
                             (int)smem);
        // persistent-style grid; per-block chunk rounded to iter size
        int per_blk = (E + NBLK_PERSIST - 1) / NBLK_PERSIST;
        per_blk = (per_blk + EDGES_PER_ITER - 1) & ~(EDGES_PER_ITER - 1);
        int nblk = (E + per_blk - 1) / per_blk;
        edge_kernel_smem<<<nblk, BLK, smem>>>(
            dist, src, dst, cutoffs, means, scaling, out, E, nwords, per_blk);
    } else {
        int blocks = (E + 511) / 512;
        edge_kernel_fb<<<blocks, BLK>>>(
            feat, dist, src, dst, cutoffs, means, scaling, ftu, out,
            E, mode == 1);
    }
}